// round 4
// baseline (speedup 1.0000x reference)
#include <cuda_runtime.h>

// MovementEmbeddingModule: bs=4, d=16, K=10, C=3, h=w=128
// out: (bs, K*6, d, h, w) float32
// Constant-step grid sample => constant bilinear weights + integer shift.
// Horizontally-prefiltered row rolling; zero-fill boundary loads; STG.128.

#define WIDTH  128
#define HEIGHT 128
#define KNUM   10
#define DNUM   16
#define CNUM   3
#define BSNUM  4
#define RPW    16   // rows per warp

__global__ __launch_bounds__(128, 8) void movement_kernel(
    const float* __restrict__ kp_app,   // (4,1,10,2)
    const float* __restrict__ kp_vid,   // (4,16,10,2)
    const float* __restrict__ img,      // (4,3,1,128,128)
    float* __restrict__ out)            // (4,60,16,128,128)
{
    const int bdk = blockIdx.x;             // 0..639
    const int k   = bdk % KNUM;
    const int t   = bdk / KNUM;
    const int dd  = t % DNUM;
    const int b   = t / DNUM;

    const float2 kva = *(const float2*)(kp_app + (b * KNUM + k) * 2);
    const float2 kv  = *(const float2*)(kp_vid + ((b * DNUM + dd) * KNUM + k) * 2);
    const float2 kv0 = *(const float2*)(kp_vid + ((b * DNUM + 0)  * KNUM + k) * 2);

    const float diffx = kv.x - kv0.x;
    const float diffy = kv.y - kv0.y;
    const float mx = diffx + kva.x;
    const float my = diffy + kva.y;
    const float vdx = -diffx;
    const float vdy = -diffy;

    const int lane = threadIdx.x & 31;
    const int warp = threadIdx.x >> 5;      // 0..3
    const int x0   = lane * 4;
    const int ybase = blockIdx.y * (4 * RPW) + warp * RPW;

    // ---- constant bilinear weights + integer shift (x) ----
    const float xi0 = vdx * 63.5f;
    const float fx  = floorf(xi0);
    const float wx1 = xi0 - fx;
    const float wx0 = 1.0f - wx1;
    const int   c0  = (int)fx + x0;         // source column of corner 0 for pixel i=0

    // ---- constant weights + shift (y) ----
    const float yi0 = vdy * 63.5f;
    const float fy  = floorf(yi0);
    const float wy1 = yi0 - fy;
    const float wy0 = 1.0f - wy1;
    const int   iyb = (int)fy;

    // ---- factored heatmap x-terms ----
    float exd[4], ex0[4];
    #pragma unroll
    for (int i = 0; i < 4; ++i) {
        const float gx = fmaf((float)(x0 + i), 2.0f / 127.0f, -1.0f);
        const float dm = gx - mx;    exd[i] = __expf(-50.0f * dm * dm);
        const float da = gx - kva.x; ex0[i] = __expf(-50.0f * da * da);
    }

    const float* imgb = img + (size_t)b * CNUM * HEIGHT * WIDTH;
    const int chStride = DNUM * HEIGHT * WIDTH;
    float* outb = out
        + ((size_t)(b * (KNUM * 6) + k * 6) * DNUM + dd) * (size_t)(HEIGHT * WIDTH)
        + x0;

    const float4 vdx4 = make_float4(vdx, vdx, vdx, vdx);
    const float4 vdy4 = make_float4(vdy, vdy, vdy, vdy);

    // load row 'row' (clamped only for validity masking = zero fill),
    // horizontal-filter into h[3][4]
    auto loadrow = [&](int row, float (*h)[4]) {
        #pragma unroll
        for (int ch = 0; ch < 3; ++ch) {
            const float* p = imgb + ch * (HEIGHT * WIDTH) + row * WIDTH;
            float v[5];
            #pragma unroll
            for (int j = 0; j < 5; ++j) {
                const int c = c0 + j;
                v[j] = (c >= 0 && c < WIDTH) ? __ldg(p + c) : 0.0f;
            }
            #pragma unroll
            for (int i = 0; i < 4; ++i)
                h[ch][i] = wx0 * v[i] + wx1 * v[i + 1];
        }
    };

    float toph[3][4], both[3][4];
    {
        const int rt  = iyb + ybase;
        const int rtc = min(max(rt, 0), HEIGHT - 1);
        loadrow(rtc, toph);
    }

    #pragma unroll 2
    for (int r = 0; r < RPW; ++r) {
        const int y  = ybase + r;
        const int rt = iyb + y;
        const int rb = rt + 1;
        const float wyt = (rt >= 0 && rt < HEIGHT) ? wy0 : 0.0f;
        const float wyb = (rb >= 0 && rb < HEIGHT) ? wy1 : 0.0f;
        const int rbc = min(max(rb, 0), HEIGHT - 1);

        loadrow(rbc, both);

        // heatmap
        const float gy  = fmaf((float)y, 2.0f / 127.0f, -1.0f);
        const float dym = gy - my;    const float eyd = __expf(-50.0f * dym * dym);
        const float dya = gy - kva.y; const float eya = __expf(-50.0f * dya * dya);
        float4 hm;
        hm.x = eyd * exd[0] - eya * ex0[0];
        hm.y = eyd * exd[1] - eya * ex0[1];
        hm.z = eyd * exd[2] - eya * ex0[2];
        hm.w = eyd * exd[3] - eya * ex0[3];

        // vertical 2-tap on prefiltered rows
        float4 dv[3];
        #pragma unroll
        for (int ch = 0; ch < 3; ++ch) {
            dv[ch].x = wyt * toph[ch][0] + wyb * both[ch][0];
            dv[ch].y = wyt * toph[ch][1] + wyb * both[ch][1];
            dv[ch].z = wyt * toph[ch][2] + wyb * both[ch][2];
            dv[ch].w = wyt * toph[ch][3] + wyb * both[ch][3];
        }

        float* o = outb + y * WIDTH;
        *(float4*)(o)                = hm;
        *(float4*)(o + chStride)     = vdx4;
        *(float4*)(o + 2 * chStride) = vdy4;
        *(float4*)(o + 3 * chStride) = dv[0];
        *(float4*)(o + 4 * chStride) = dv[1];
        *(float4*)(o + 5 * chStride) = dv[2];

        // rotate prefiltered rows
        #pragma unroll
        for (int ch = 0; ch < 3; ++ch)
            #pragma unroll
            for (int i = 0; i < 4; ++i) toph[ch][i] = both[ch][i];
    }
}

extern "C" void kernel_launch(void* const* d_in, const int* in_sizes, int n_in,
                              void* d_out, int out_size) {
    const float* kp_app = nullptr;   // 80
    const float* kp_vid = nullptr;   // 1280
    const float* img    = nullptr;   // 196608
    for (int i = 0; i < n_in; ++i) {
        if (in_sizes[i] == BSNUM * 1 * KNUM * 2)               kp_app = (const float*)d_in[i];
        else if (in_sizes[i] == BSNUM * DNUM * KNUM * 2)       kp_vid = (const float*)d_in[i];
        else if (in_sizes[i] == BSNUM * CNUM * HEIGHT * WIDTH) img    = (const float*)d_in[i];
    }
    float* out = (float*)d_out;

    dim3 grid(BSNUM * DNUM * KNUM, HEIGHT / (4 * RPW), 1);   // 640 x 2
    dim3 block(128, 1, 1);
    movement_kernel<<<grid, block>>>(kp_app, kp_vid, img, out);
}

// round 5
// speedup vs baseline: 1.0651x; 1.0651x over previous
#include <cuda_runtime.h>

// MovementEmbeddingModule: bs=4, d=16, K=10, C=3, h=w=128
// out: (bs, K*6, d, h, w) float32
// Constant-step grid sample => constant bilinear weights + integer shift.
// Hoisted clamped indices + masked x-weights (computed once per thread),
// horizontally-prefiltered row rolling, STG.128, 8 CTAs/SM.

#define WIDTH  128
#define HEIGHT 128
#define KNUM   10
#define DNUM   16
#define CNUM   3
#define BSNUM  4
#define RPW    8    // rows per warp

__global__ __launch_bounds__(128, 8) void movement_kernel(
    const float* __restrict__ kp_app,   // (4,1,10,2)
    const float* __restrict__ kp_vid,   // (4,16,10,2)
    const float* __restrict__ img,      // (4,3,1,128,128)
    float* __restrict__ out)            // (4,60,16,128,128)
{
    const int bdk = blockIdx.x;             // 0..639
    const int k   = bdk % KNUM;
    const int t   = bdk / KNUM;
    const int dd  = t % DNUM;
    const int b   = t / DNUM;

    const float2 kva = *(const float2*)(kp_app + (b * KNUM + k) * 2);
    const float2 kv  = *(const float2*)(kp_vid + ((b * DNUM + dd) * KNUM + k) * 2);
    const float2 kv0 = *(const float2*)(kp_vid + ((b * DNUM + 0)  * KNUM + k) * 2);

    const float diffx = kv.x - kv0.x;
    const float diffy = kv.y - kv0.y;
    const float mx = diffx + kva.x;
    const float my = diffy + kva.y;
    const float vdx = -diffx;
    const float vdy = -diffy;

    const int lane = threadIdx.x & 31;
    const int warp = threadIdx.x >> 5;      // 0..3
    const int x0   = lane * 4;
    const int ybase = blockIdx.y * (4 * RPW) + warp * RPW;

    // ---- constant bilinear weights + integer shift (x), hoisted ----
    const float xi0 = vdx * 63.5f;
    const float fx  = floorf(xi0);
    const float wx1 = xi0 - fx;
    const float wx0 = 1.0f - wx1;
    const int   c0  = (int)fx + x0;

    int cc[5];
    float mw0[4], mw1[4];
    #pragma unroll
    for (int j = 0; j < 5; ++j) cc[j] = min(max(c0 + j, 0), WIDTH - 1);
    #pragma unroll
    for (int i = 0; i < 4; ++i) {
        const int ci0 = c0 + i, ci1 = ci0 + 1;
        mw0[i] = (ci0 >= 0 && ci0 < WIDTH) ? wx0 : 0.0f;
        mw1[i] = (ci1 >= 0 && ci1 < WIDTH) ? wx1 : 0.0f;
    }

    // ---- constant weights + shift (y) ----
    const float yi0 = vdy * 63.5f;
    const float fy  = floorf(yi0);
    const float wy1 = yi0 - fy;
    const float wy0 = 1.0f - wy1;
    const int   iyb = (int)fy;

    // ---- factored heatmap x-terms ----
    float exd[4], ex0[4];
    #pragma unroll
    for (int i = 0; i < 4; ++i) {
        const float gx = fmaf((float)(x0 + i), 2.0f / 127.0f, -1.0f);
        const float dm = gx - mx;    exd[i] = __expf(-50.0f * dm * dm);
        const float da = gx - kva.x; ex0[i] = __expf(-50.0f * da * da);
    }

    const float* imgb = img + (size_t)b * CNUM * HEIGHT * WIDTH;
    const int chStride = DNUM * HEIGHT * WIDTH;
    float* outb = out
        + ((size_t)(b * (KNUM * 6) + k * 6) * DNUM + dd) * (size_t)(HEIGHT * WIDTH)
        + x0;

    const float4 vdx4 = make_float4(vdx, vdx, vdx, vdx);
    const float4 vdy4 = make_float4(vdy, vdy, vdy, vdy);

    // load clamped row, horizontal-prefilter into h[3][4] (masked weights)
    auto loadrow = [&](int rowc, float (*h)[4]) {
        #pragma unroll
        for (int ch = 0; ch < 3; ++ch) {
            const float* p = imgb + ch * (HEIGHT * WIDTH) + rowc * WIDTH;
            float v[5];
            #pragma unroll
            for (int j = 0; j < 5; ++j) v[j] = __ldg(p + cc[j]);
            #pragma unroll
            for (int i = 0; i < 4; ++i)
                h[ch][i] = mw0[i] * v[i] + mw1[i] * v[i + 1];
        }
    };

    float toph[3][4], both[3][4];
    {
        const int rt  = iyb + ybase;
        loadrow(min(max(rt, 0), HEIGHT - 1), toph);
    }

    #pragma unroll 2
    for (int r = 0; r < RPW; ++r) {
        const int y  = ybase + r;
        const int rt = iyb + y;
        const int rb = rt + 1;
        const float wyt = (rt >= 0 && rt < HEIGHT) ? wy0 : 0.0f;
        const float wyb = (rb >= 0 && rb < HEIGHT) ? wy1 : 0.0f;

        loadrow(min(max(rb, 0), HEIGHT - 1), both);

        // heatmap (factored Gaussian)
        const float gy  = fmaf((float)y, 2.0f / 127.0f, -1.0f);
        const float dym = gy - my;    const float eyd = __expf(-50.0f * dym * dym);
        const float dya = gy - kva.y; const float eya = __expf(-50.0f * dya * dya);
        float4 hm;
        hm.x = eyd * exd[0] - eya * ex0[0];
        hm.y = eyd * exd[1] - eya * ex0[1];
        hm.z = eyd * exd[2] - eya * ex0[2];
        hm.w = eyd * exd[3] - eya * ex0[3];

        // vertical 2-tap on prefiltered rows
        float4 dv[3];
        #pragma unroll
        for (int ch = 0; ch < 3; ++ch) {
            dv[ch].x = wyt * toph[ch][0] + wyb * both[ch][0];
            dv[ch].y = wyt * toph[ch][1] + wyb * both[ch][1];
            dv[ch].z = wyt * toph[ch][2] + wyb * both[ch][2];
            dv[ch].w = wyt * toph[ch][3] + wyb * both[ch][3];
        }

        float* o = outb + y * WIDTH;
        *(float4*)(o)                = hm;
        *(float4*)(o + chStride)     = vdx4;
        *(float4*)(o + 2 * chStride) = vdy4;
        *(float4*)(o + 3 * chStride) = dv[0];
        *(float4*)(o + 4 * chStride) = dv[1];
        *(float4*)(o + 5 * chStride) = dv[2];

        // rotate prefiltered rows
        #pragma unroll
        for (int ch = 0; ch < 3; ++ch)
            #pragma unroll
            for (int i = 0; i < 4; ++i) toph[ch][i] = both[ch][i];
    }
}

extern "C" void kernel_launch(void* const* d_in, const int* in_sizes, int n_in,
                              void* d_out, int out_size) {
    const float* kp_app = nullptr;   // 80
    const float* kp_vid = nullptr;   // 1280
    const float* img    = nullptr;   // 196608
    for (int i = 0; i < n_in; ++i) {
        if (in_sizes[i] == BSNUM * 1 * KNUM * 2)               kp_app = (const float*)d_in[i];
        else if (in_sizes[i] == BSNUM * DNUM * KNUM * 2)       kp_vid = (const float*)d_in[i];
        else if (in_sizes[i] == BSNUM * CNUM * HEIGHT * WIDTH) img    = (const float*)d_in[i];
    }
    float* out = (float*)d_out;

    dim3 grid(BSNUM * DNUM * KNUM, HEIGHT / (4 * RPW), 1);   // 640 x 4
    dim3 block(128, 1, 1);
    movement_kernel<<<grid, block>>>(kp_app, kp_vid, img, out);
}